// round 1
// baseline (speedup 1.0000x reference)
#include <cuda_runtime.h>
#include <math.h>

#define NQ   10
#define NL   4
#define DIM  1024
#define NTHR 512
#define PI_F 3.14159265358979f

__device__ __forceinline__ float2 cmul(float2 a, float2 b) {
    return make_float2(a.x*b.x - a.y*b.y, a.x*b.y + a.y*b.x);
}

// CNOT ring (CNOT(0,1)..CNOT(8,9), CNOT(9,0)) as a basis-state permutation.
// Qubit q lives at flat bit (9-q). New qubit values are prefix-XORs over
// qubit order == suffix-XORs over flat bits.
__device__ __forceinline__ int perm_f(int i) {
    int s = i;
    s ^= s >> 1; s ^= s >> 2; s ^= s >> 4; s ^= s >> 8;   // s_j = XOR of bits j..9
    int low = s & 0x1FF;                                   // new flat bits 0..8
    int hi  = ((s ^ (i >> 9)) & 1) << 9;                   // new bit9 = XOR bits 0..8
    return low | hi;
}

__global__ __launch_bounds__(NTHR) void qsim_kernel(
    const float* __restrict__ xin,   // [B, NQ]
    const float* __restrict__ wts,   // [NL, NQ, 3]
    float* __restrict__ out)         // [B, NQ]
{
    __shared__ float2 st[DIM];
    __shared__ float2 W[NQ][4];
    __shared__ float  zacc[NQ];

    const int b = blockIdx.x;
    const int t = threadIdx.x;

    // |0...0>
    st[t]        = make_float2(t == 0 ? 1.0f : 0.0f, 0.0f);
    st[t + NTHR] = make_float2(0.0f, 0.0f);
    if (t < NQ) zacc[t] = 0.0f;

    for (int l = 0; l < NL; ++l) {
        // Threads 0..9: build fused gate W_q = RZ(w2)*RY(w1)*RX(w0)*RY(clip(x_q))
        if (t < NQ) {
            const int q = t;
            const float* wq = wts + (l * NQ + q) * 3;
            float s0, c0, s1, c1, s2, c2;
            sincosf(0.5f * wq[0], &s0, &c0);
            sincosf(0.5f * wq[1], &s1, &c1);
            sincosf(0.5f * wq[2], &s2, &c2);
            // M = RY(w1)*RX(w0)
            float2 M00 = make_float2( c1*c0,  s1*s0);
            float2 M01 = make_float2(-s1*c0, -c1*s0);
            float2 M10 = make_float2( s1*c0, -c1*s0);
            float2 M11 = make_float2( c1*c0, -s1*s0);
            // U = RZ(w2)*M : row0 *= e^{-i w2/2}, row1 *= e^{+i w2/2}
            float2 e0 = make_float2(c2, -s2);
            float2 e1 = make_float2(c2,  s2);
            float2 U00 = cmul(e0, M00), U01 = cmul(e0, M01);
            float2 U10 = cmul(e1, M10), U11 = cmul(e1, M11);
            // W = U * RY(x_q), RY real: [[cx,-sx],[sx,cx]]
            float xv = xin[b * NQ + q];
            xv = fminf(fmaxf(xv, -PI_F), PI_F);
            float sx, cx;
            sincosf(0.5f * xv, &sx, &cx);
            W[q][0] = make_float2( U00.x*cx + U01.x*sx,  U00.y*cx + U01.y*sx);
            W[q][1] = make_float2(-U00.x*sx + U01.x*cx, -U00.y*sx + U01.y*cx);
            W[q][2] = make_float2( U10.x*cx + U11.x*sx,  U10.y*cx + U11.y*sx);
            W[q][3] = make_float2(-U10.x*sx + U11.x*cx, -U10.y*sx + U11.y*cx);
        }
        __syncthreads();

        // 10 fused single-qubit gates. Each thread owns a disjoint (i0,i1)
        // pair per gate, so only inter-gate syncs are needed.
        #pragma unroll
        for (int q = 0; q < NQ; ++q) {
            const int k = 9 - q;
            const int lowmask = (1 << k) - 1;
            const int i0 = ((t & ~lowmask) << 1) | (t & lowmask);
            const int i1 = i0 | (1 << k);
            float2 a0 = st[i0], a1 = st[i1];
            float2 w00 = W[q][0], w01 = W[q][1], w10 = W[q][2], w11 = W[q][3];
            float2 n0, n1;
            n0.x = w00.x*a0.x - w00.y*a0.y + w01.x*a1.x - w01.y*a1.y;
            n0.y = w00.x*a0.y + w00.y*a0.x + w01.x*a1.y + w01.y*a1.x;
            n1.x = w10.x*a0.x - w10.y*a0.y + w11.x*a1.x - w11.y*a1.y;
            n1.y = w10.x*a0.y + w10.y*a0.x + w11.x*a1.y + w11.y*a1.x;
            st[i0] = n0; st[i1] = n1;
            __syncthreads();
        }

        // CNOT ring: register-buffered permutation (bijective scatter)
        float2 a = st[t], c = st[t + NTHR];
        const int f0 = perm_f(t), f1 = perm_f(t + NTHR);
        __syncthreads();
        st[f0] = a; st[f1] = c;
        __syncthreads();
    }

    // <Z_q> = sum_i p_i * (1 - 2*bit_{9-q}(i))
    float2 a0 = st[t], a1 = st[t + NTHR];
    float p0 = a0.x*a0.x + a0.y*a0.y;
    float p1 = a1.x*a1.x + a1.y*a1.y;
    float z[NQ];
    z[0] = p0 - p1;                 // qubit 0 = flat bit 9 (set iff index >= 512)
    const float s = p0 + p1;        // indices t and t+512 share bits 0..8
    #pragma unroll
    for (int q = 1; q < NQ; ++q)
        z[q] = ((t >> (9 - q)) & 1) ? -s : s;

    #pragma unroll
    for (int q = 0; q < NQ; ++q) {
        float v = z[q];
        #pragma unroll
        for (int off = 16; off > 0; off >>= 1)
            v += __shfl_xor_sync(0xFFFFFFFFu, v, off);
        if ((t & 31) == 0) atomicAdd(&zacc[q], v);
    }
    __syncthreads();
    if (t < NQ) out[b * NQ + t] = zacc[t];
}

extern "C" void kernel_launch(void* const* d_in, const int* in_sizes, int n_in,
                              void* d_out, int out_size) {
    const float* xin = (const float*)d_in[0];   // inputs  [B, 10] f32
    const float* wts = (const float*)d_in[1];   // weights [4, 10, 3] f32
    float* out = (float*)d_out;                 // [B, 10] f32
    const int batch = in_sizes[0] / NQ;
    qsim_kernel<<<batch, NTHR>>>(xin, wts, out);
}

// round 2
// speedup vs baseline: 2.3000x; 2.3000x over previous
#include <cuda_runtime.h>
#include <math.h>

#define NQ   10
#define NL   4
#define NGATE (NL * NQ)
#define WPB  4                 // warps (batch elements) per block
#define NTHR (WPB * 32)
#define PI_F 3.14159265358979f

__global__ __launch_bounds__(NTHR) void qsim_reg_kernel(
    const float* __restrict__ xin,   // [B, NQ]
    const float* __restrict__ wts,   // [NL, NQ, 3]
    float* __restrict__ out,         // [B, NQ]
    int B)
{
    __shared__ float2 Wsh[WPB][NGATE][4];

    const int warp = threadIdx.x >> 5;
    const int lane = threadIdx.x & 31;
    const int b = blockIdx.x * WPB + warp;
    if (b >= B) return;

    // ---- Prologue: fused gate matrices W = RZ(w2)*RY(w1)*RX(w0)*RY(clip(x_q))
    for (int g = lane; g < NGATE; g += 32) {
        const int q = g % NQ;
        const float* wq = wts + g * 3;           // g == l*NQ + q
        float s0, c0, s1, c1, s2, c2;
        sincosf(0.5f * wq[0], &s0, &c0);
        sincosf(0.5f * wq[1], &s1, &c1);
        sincosf(0.5f * wq[2], &s2, &c2);
        // M = RY(w1)*RX(w0)
        float2 M00 = make_float2( c1*c0,  s1*s0);
        float2 M01 = make_float2(-s1*c0, -c1*s0);
        float2 M10 = make_float2( s1*c0, -c1*s0);
        float2 M11 = make_float2( c1*c0, -s1*s0);
        // U = RZ(w2)*M
        float2 U00 = make_float2(c2*M00.x + s2*M00.y, c2*M00.y - s2*M00.x);
        float2 U01 = make_float2(c2*M01.x + s2*M01.y, c2*M01.y - s2*M01.x);
        float2 U10 = make_float2(c2*M10.x - s2*M10.y, c2*M10.y + s2*M10.x);
        float2 U11 = make_float2(c2*M11.x - s2*M11.y, c2*M11.y + s2*M11.x);
        // W = U * RY(x_q)
        float xv = xin[b * NQ + q];
        xv = fminf(fmaxf(xv, -PI_F), PI_F);
        float sx, cx;
        sincosf(0.5f * xv, &sx, &cx);
        Wsh[warp][g][0] = make_float2( U00.x*cx + U01.x*sx,  U00.y*cx + U01.y*sx);
        Wsh[warp][g][1] = make_float2(-U00.x*sx + U01.x*cx, -U00.y*sx + U01.y*cx);
        Wsh[warp][g][2] = make_float2( U10.x*cx + U11.x*sx,  U10.y*cx + U11.y*sx);
        Wsh[warp][g][3] = make_float2(-U10.x*sx + U11.x*cx, -U10.y*sx + U11.y*cx);
    }
    __syncwarp();

    // ---- State: amplitude index i = (lane<<5) | r ; flat bit k of i maps
    // qubit q = 9-k. Registers hold bits 0..4, lane holds bits 5..9.
    float2 st[32];
    #pragma unroll
    for (int r = 0; r < 32; ++r) st[r] = make_float2(0.0f, 0.0f);
    if (lane == 0) st[0].x = 1.0f;

    for (int l = 0; l < NL; ++l) {
        const int base = l * NQ;

        // -- Low gates: qubits 5..9 -> register bit m = 9-q (pure registers)
        #pragma unroll
        for (int m = 4; m >= 0; --m) {
            const int q = 9 - m;
            const float2 w00 = Wsh[warp][base + q][0];
            const float2 w01 = Wsh[warp][base + q][1];
            const float2 w10 = Wsh[warp][base + q][2];
            const float2 w11 = Wsh[warp][base + q][3];
            #pragma unroll
            for (int r = 0; r < 32; ++r) {
                if (r & (1 << m)) continue;
                const int r1 = r | (1 << m);
                float2 a0 = st[r], a1 = st[r1];
                st[r].x  = w00.x*a0.x - w00.y*a0.y + w01.x*a1.x - w01.y*a1.y;
                st[r].y  = w00.x*a0.y + w00.y*a0.x + w01.x*a1.y + w01.y*a1.x;
                st[r1].x = w10.x*a0.x - w10.y*a0.y + w11.x*a1.x - w11.y*a1.y;
                st[r1].y = w10.x*a0.y + w10.y*a0.x + w11.x*a1.y + w11.y*a1.x;
            }
        }

        // -- High gates: qubits 0..4 -> lane bit m = 4-q (shuffle exchange)
        #pragma unroll
        for (int q = 0; q < 5; ++q) {
            const int m = 4 - q;
            const float2 w00 = Wsh[warp][base + q][0];
            const float2 w01 = Wsh[warp][base + q][1];
            const float2 w10 = Wsh[warp][base + q][2];
            const float2 w11 = Wsh[warp][base + q][3];
            const bool row = (lane >> m) & 1;
            // row 0: n = w00*own + w01*partner ; row 1: n = w11*own + w10*partner
            const float2 wOwn = row ? w11 : w00;
            const float2 wOth = row ? w10 : w01;
            #pragma unroll
            for (int r = 0; r < 32; ++r) {
                float2 p;
                p.x = __shfl_xor_sync(0xFFFFFFFFu, st[r].x, 1 << m);
                p.y = __shfl_xor_sync(0xFFFFFFFFu, st[r].y, 1 << m);
                const float2 a = st[r];
                st[r].x = wOwn.x*a.x - wOwn.y*a.y + wOth.x*p.x - wOth.y*p.y;
                st[r].y = wOwn.x*a.y + wOwn.y*a.x + wOth.x*p.y + wOth.y*p.x;
            }
        }

        // -- CNOT ring --
        // CNOT(0,1)..(3,4): lane-bit cascade; pull source lane = lane^(lane>>1)
        {
            const int sl = lane ^ (lane >> 1);
            #pragma unroll
            for (int r = 0; r < 32; ++r) {
                st[r].x = __shfl_sync(0xFFFFFFFFu, st[r].x, sl);
                st[r].y = __shfl_sync(0xFFFFFFFFu, st[r].y, sl);
            }
        }
        // CNOT(4,5): control = lane bit 0, target = reg bit 4
        {
            const bool cc = lane & 1;
            #pragma unroll
            for (int r = 0; r < 16; ++r) {
                const float2 a = st[r], bb = st[r + 16];
                st[r]      = cc ? bb : a;
                st[r + 16] = cc ? a  : bb;
            }
        }
        // CNOT(5,6)..(8,9): static register permutation dst[r] <- src[r^(r>>1)]
        {
            float2 tmp[32];
            #pragma unroll
            for (int r = 0; r < 32; ++r) tmp[r] = st[r ^ (r >> 1)];
            #pragma unroll
            for (int r = 0; r < 32; ++r) st[r] = tmp[r];
        }
        // CNOT(9,0): control = reg bit 0, target = lane bit 4
        #pragma unroll
        for (int r = 1; r < 32; r += 2) {
            st[r].x = __shfl_xor_sync(0xFFFFFFFFu, st[r].x, 16);
            st[r].y = __shfl_xor_sync(0xFFFFFFFFu, st[r].y, 16);
        }
    }

    // ---- Expectation values <Z_q> = P(bit=0) - P(bit=1)
    float v0[32];
    #pragma unroll
    for (int r = 0; r < 32; ++r) v0[r] = st[r].x*st[r].x + st[r].y*st[r].y;

    float zr[5];   // signed sums over register bits 0..4
    float v1[16], v2[8], v3[4], v4[2];
    {
        float d = 0.f;
        #pragma unroll
        for (int k = 0; k < 16; ++k) { d += v0[2*k] - v0[2*k+1]; v1[k] = v0[2*k] + v0[2*k+1]; }
        zr[0] = d;
        d = 0.f;
        #pragma unroll
        for (int k = 0; k < 8; ++k)  { d += v1[2*k] - v1[2*k+1]; v2[k] = v1[2*k] + v1[2*k+1]; }
        zr[1] = d;
        d = 0.f;
        #pragma unroll
        for (int k = 0; k < 4; ++k)  { d += v2[2*k] - v2[2*k+1]; v3[k] = v2[2*k] + v2[2*k+1]; }
        zr[2] = d;
        d = 0.f;
        #pragma unroll
        for (int k = 0; k < 2; ++k)  { d += v3[2*k] - v3[2*k+1]; v4[k] = v3[2*k] + v3[2*k+1]; }
        zr[3] = d;
        zr[4] = v4[0] - v4[1];
    }
    const float s_tot = v4[0] + v4[1];

    // z[q]: qubits 0..4 live on lane bit (4-q); qubits 5..9 are zr[9-q]
    float z[NQ];
    #pragma unroll
    for (int q = 0; q < 5; ++q)
        z[q] = ((lane >> (4 - q)) & 1) ? -s_tot : s_tot;
    #pragma unroll
    for (int q = 5; q < NQ; ++q)
        z[q] = zr[9 - q];

    #pragma unroll
    for (int q = 0; q < NQ; ++q) {
        float v = z[q];
        #pragma unroll
        for (int off = 16; off > 0; off >>= 1)
            v += __shfl_xor_sync(0xFFFFFFFFu, v, off);
        z[q] = v;
    }
    if (lane == 0) {
        #pragma unroll
        for (int q = 0; q < NQ; ++q) out[b * NQ + q] = z[q];
    }
}

extern "C" void kernel_launch(void* const* d_in, const int* in_sizes, int n_in,
                              void* d_out, int out_size) {
    const float* xin = (const float*)d_in[0];   // [B, 10] f32
    const float* wts = (const float*)d_in[1];   // [4, 10, 3] f32
    float* out = (float*)d_out;                 // [B, 10] f32
    const int batch = in_sizes[0] / NQ;
    const int blocks = (batch + WPB - 1) / WPB;
    qsim_reg_kernel<<<blocks, NTHR>>>(xin, wts, out, batch);
}

// round 3
// speedup vs baseline: 2.8583x; 1.2427x over previous
#include <cuda_runtime.h>
#include <math.h>

#define NQ   10
#define NL   4
#define NGATE (NL * NQ)
#define WPB  4
#define NTHR (WPB * 32)
#define PI_F 3.14159265358979f
#define FULLM 0xFFFFFFFFu

typedef unsigned long long u64t;

// ---- f32x2 packed helpers (Blackwell packed-FMA pipe, PTX-only) ----
__device__ __forceinline__ u64t pk(float lo, float hi) {
    u64t r; asm("mov.b64 %0, {%1, %2};" : "=l"(r) : "f"(lo), "f"(hi)); return r;
}
__device__ __forceinline__ void unpk(u64t u, float& lo, float& hi) {
    asm("mov.b64 {%0, %1}, %2;" : "=f"(lo), "=f"(hi) : "l"(u));
}
__device__ __forceinline__ u64t ffma2(u64t a, u64t b, u64t c) {
    u64t r; asm("fma.rn.f32x2 %0, %1, %2, %3;" : "=l"(r) : "l"(a), "l"(b), "l"(c)); return r;
}
__device__ __forceinline__ u64t fmul2(u64t a, u64t b) {
    u64t r; asm("mul.rn.f32x2 %0, %1, %2;" : "=l"(r) : "l"(a), "l"(b)); return r;
}

__global__ __launch_bounds__(NTHR) void qsim_f32x2_kernel(
    const float* __restrict__ xin,   // [B, NQ]
    const float* __restrict__ wts,   // [NL, NQ, 3]
    float* __restrict__ out,         // [B, NQ]
    int B)
{
    // Packed weight table per warp per gate:
    //  [0..3]  dup(w00.x), dup(w01.x), dup(w10.x), dup(w11.x)
    //  [4..7]  dup(w00.y), dup(w01.y), dup(w10.y), dup(w11.y)
    //  [8..11] dup(-w00.y), dup(-w01.y), dup(-w10.y), dup(-w11.y)
    //  [12..17] cross packs for the intra-pair (bit0) gate
    __shared__ u64t Wt[WPB][NGATE][18];

    const int warp = threadIdx.x >> 5;
    const int lane = threadIdx.x & 31;
    const int b = blockIdx.x * WPB + warp;
    if (b >= B) return;

    // ---- Prologue: fused W = RZ(w2)*RY(w1)*RX(w0)*RY(clip(x_q)), packed forms
    for (int g = lane; g < NGATE; g += 32) {
        const int q = g % NQ;
        const float* wq = wts + g * 3;
        float s0, c0, s1, c1, s2, c2;
        sincosf(0.5f * wq[0], &s0, &c0);
        sincosf(0.5f * wq[1], &s1, &c1);
        sincosf(0.5f * wq[2], &s2, &c2);
        float2 M00 = make_float2( c1*c0,  s1*s0);
        float2 M01 = make_float2(-s1*c0, -c1*s0);
        float2 M10 = make_float2( s1*c0, -c1*s0);
        float2 M11 = make_float2( c1*c0, -s1*s0);
        float2 U00 = make_float2(c2*M00.x + s2*M00.y, c2*M00.y - s2*M00.x);
        float2 U01 = make_float2(c2*M01.x + s2*M01.y, c2*M01.y - s2*M01.x);
        float2 U10 = make_float2(c2*M10.x - s2*M10.y, c2*M10.y + s2*M10.x);
        float2 U11 = make_float2(c2*M11.x - s2*M11.y, c2*M11.y + s2*M11.x);
        float xv = xin[b * NQ + q];
        xv = fminf(fmaxf(xv, -PI_F), PI_F);
        float sx, cx;
        sincosf(0.5f * xv, &sx, &cx);
        float2 w00 = make_float2( U00.x*cx + U01.x*sx,  U00.y*cx + U01.y*sx);
        float2 w01 = make_float2(-U00.x*sx + U01.x*cx, -U00.y*sx + U01.y*cx);
        float2 w10 = make_float2( U10.x*cx + U11.x*sx,  U10.y*cx + U11.y*sx);
        float2 w11 = make_float2(-U10.x*sx + U11.x*cx, -U10.y*sx + U11.y*cx);

        u64t* T = Wt[warp][g];
        T[0]  = pk(w00.x, w00.x); T[1]  = pk(w01.x, w01.x);
        T[2]  = pk(w10.x, w10.x); T[3]  = pk(w11.x, w11.x);
        T[4]  = pk(w00.y, w00.y); T[5]  = pk(w01.y, w01.y);
        T[6]  = pk(w10.y, w10.y); T[7]  = pk(w11.y, w11.y);
        T[8]  = pk(-w00.y, -w00.y); T[9]  = pk(-w01.y, -w01.y);
        T[10] = pk(-w10.y, -w10.y); T[11] = pk(-w11.y, -w11.y);
        T[12] = pk(w00.x, w11.x);   T[13] = pk(w01.x, w10.x);
        T[14] = pk(w00.y, w11.y);   T[15] = pk(w01.y, w10.y);
        T[16] = pk(-w00.y, -w11.y); T[17] = pk(-w01.y, -w10.y);
    }
    __syncwarp();

    // ---- State: amplitude i = (lane<<5)|(j<<1)|h.
    // sre[j] packs (re[2j], re[2j+1]); sim[j] likewise. Qubit q = flat bit 9-q.
    u64t sre[16], sim[16];
    #pragma unroll
    for (int j = 0; j < 16; ++j) { sre[j] = 0ull; sim[j] = 0ull; }
    if (lane == 0) sre[0] = pk(1.0f, 0.0f);

    for (int l = 0; l < NL; ++l) {
        const int base = l * NQ;

        // -- Qubit 9 (flat bit 0): intra-pair gate via cross packs + half swap
        {
            const u64t* T = Wt[warp][base + 9];
            u64t A = T[12], Bp = T[13], C = T[14], D = T[15], Cn = T[16], Dn = T[17];
            #pragma unroll
            for (int j = 0; j < 16; ++j) {
                u64t are = sre[j], aim = sim[j];
                float arl, arh, ail, aih;
                unpk(are, arl, arh); unpk(aim, ail, aih);
                u64t srs = pk(arh, arl), sis = pk(aih, ail);
                sre[j] = ffma2(A, are, ffma2(Cn, aim, ffma2(Bp, srs, fmul2(Dn, sis))));
                sim[j] = ffma2(A, aim, ffma2(C, are, ffma2(Bp, sis, fmul2(D, srs))));
            }
        }

        // -- Qubits 8..5 (flat bits 1..4): packed register butterflies
        #pragma unroll
        for (int q = 8; q >= 5; --q) {
            const int pb = 8 - q;                 // pair-index bit
            const u64t* T = Wt[warp][base + q];
            u64t x00 = T[0], x01 = T[1], x10 = T[2], x11 = T[3];
            u64t y00 = T[4], y01 = T[5], y10 = T[6], y11 = T[7];
            u64t n00 = T[8], n01 = T[9], n10 = T[10], n11 = T[11];
            #pragma unroll
            for (int j0 = 0; j0 < 16; ++j0) {
                if (j0 & (1 << pb)) continue;
                const int j1 = j0 | (1 << pb);
                u64t a0r = sre[j0], a0i = sim[j0], a1r = sre[j1], a1i = sim[j1];
                sre[j0] = ffma2(x00, a0r, ffma2(n00, a0i, ffma2(x01, a1r, fmul2(n01, a1i))));
                sim[j0] = ffma2(x00, a0i, ffma2(y00, a0r, ffma2(x01, a1i, fmul2(y01, a1r))));
                sre[j1] = ffma2(x10, a0r, ffma2(n10, a0i, ffma2(x11, a1r, fmul2(n11, a1i))));
                sim[j1] = ffma2(x10, a0i, ffma2(y10, a0r, ffma2(x11, a1i, fmul2(y11, a1r))));
            }
        }

        // -- Qubits 0..4 (lane bits 4..0): shuffle exchange + packed FMA
        #pragma unroll
        for (int q = 0; q < 5; ++q) {
            const int lb = 4 - q;
            const u64t* T = Wt[warp][base + q];
            const bool row = (lane >> lb) & 1;
            const int oi = row ? 3 : 0, pi = row ? 2 : 1;
            u64t ownx = T[oi], othx = T[pi];
            u64t owny = T[4 + oi], othy = T[4 + pi];
            u64t ownny = T[8 + oi], othny = T[8 + pi];
            #pragma unroll
            for (int j = 0; j < 16; ++j) {
                float al, ah, il, ih;
                unpk(sre[j], al, ah); unpk(sim[j], il, ih);
                float prl = __shfl_xor_sync(FULLM, al, 1 << lb);
                float prh = __shfl_xor_sync(FULLM, ah, 1 << lb);
                float pil = __shfl_xor_sync(FULLM, il, 1 << lb);
                float pih = __shfl_xor_sync(FULLM, ih, 1 << lb);
                u64t pre = pk(prl, prh), pim = pk(pil, pih);
                u64t are = sre[j], aim = sim[j];
                sre[j] = ffma2(ownx, are, ffma2(ownny, aim, ffma2(othx, pre, fmul2(othny, pim))));
                sim[j] = ffma2(ownx, aim, ffma2(owny, are, ffma2(othx, pim, fmul2(othy, pre))));
            }
        }

        // -- CNOT ring --
        // CNOT(0,1)..(3,4): lane-bit cascade, pull from lane^(lane>>1)
        {
            const int sl = lane ^ (lane >> 1);
            #pragma unroll
            for (int j = 0; j < 16; ++j) {
                float al, ah, il, ih;
                unpk(sre[j], al, ah); unpk(sim[j], il, ih);
                al = __shfl_sync(FULLM, al, sl); ah = __shfl_sync(FULLM, ah, sl);
                il = __shfl_sync(FULLM, il, sl); ih = __shfl_sync(FULLM, ih, sl);
                sre[j] = pk(al, ah); sim[j] = pk(il, ih);
            }
        }
        // CNOT(4,5): control = lane bit 0, target = flat bit 4 (j bit 3)
        {
            const bool cc = lane & 1;
            #pragma unroll
            for (int j = 0; j < 8; ++j) {
                u64t a = sre[j], bb = sre[j + 8];
                sre[j] = cc ? bb : a; sre[j + 8] = cc ? a : bb;
                u64t c = sim[j], d = sim[j + 8];
                sim[j] = cc ? d : c; sim[j + 8] = cc ? c : d;
            }
        }
        // CNOT(5,6)..(8,9): static permutation dst[r] <- src[r^(r>>1)], 5-bit r
        {
            float fr[32], fi[32];
            #pragma unroll
            for (int j = 0; j < 16; ++j) {
                unpk(sre[j], fr[2 * j], fr[2 * j + 1]);
                unpk(sim[j], fi[2 * j], fi[2 * j + 1]);
            }
            #pragma unroll
            for (int j = 0; j < 16; ++j) {
                const int r0 = 2 * j, r1 = 2 * j + 1;
                const int s0 = r0 ^ (r0 >> 1), s1 = r1 ^ (r1 >> 1);
                sre[j] = pk(fr[s0], fr[s1]);
                sim[j] = pk(fi[s0], fi[s1]);
            }
        }
        // CNOT(9,0): control = flat bit 0 (hi half), target = lane bit 4
        #pragma unroll
        for (int j = 0; j < 16; ++j) {
            float al, ah, il, ih;
            unpk(sre[j], al, ah); unpk(sim[j], il, ih);
            ah = __shfl_xor_sync(FULLM, ah, 16);
            ih = __shfl_xor_sync(FULLM, ih, 16);
            sre[j] = pk(al, ah); sim[j] = pk(il, ih);
        }
    }

    // ---- Expectation values
    float v0[32];
    #pragma unroll
    for (int j = 0; j < 16; ++j) {
        u64t p = ffma2(sim[j], sim[j], fmul2(sre[j], sre[j]));
        unpk(p, v0[2 * j], v0[2 * j + 1]);
    }

    float zr[5];
    float v1[16], v2[8], v3[4], v4[2];
    {
        float d = 0.f;
        #pragma unroll
        for (int k = 0; k < 16; ++k) { d += v0[2*k] - v0[2*k+1]; v1[k] = v0[2*k] + v0[2*k+1]; }
        zr[0] = d;
        d = 0.f;
        #pragma unroll
        for (int k = 0; k < 8; ++k)  { d += v1[2*k] - v1[2*k+1]; v2[k] = v1[2*k] + v1[2*k+1]; }
        zr[1] = d;
        d = 0.f;
        #pragma unroll
        for (int k = 0; k < 4; ++k)  { d += v2[2*k] - v2[2*k+1]; v3[k] = v2[2*k] + v2[2*k+1]; }
        zr[2] = d;
        d = 0.f;
        #pragma unroll
        for (int k = 0; k < 2; ++k)  { d += v3[2*k] - v3[2*k+1]; v4[k] = v3[2*k] + v3[2*k+1]; }
        zr[3] = d;
        zr[4] = v4[0] - v4[1];
    }
    const float s_tot = v4[0] + v4[1];

    float z[NQ];
    #pragma unroll
    for (int q = 0; q < 5; ++q)
        z[q] = ((lane >> (4 - q)) & 1) ? -s_tot : s_tot;
    #pragma unroll
    for (int q = 5; q < NQ; ++q)
        z[q] = zr[9 - q];

    #pragma unroll
    for (int q = 0; q < NQ; ++q) {
        float v = z[q];
        #pragma unroll
        for (int off = 16; off > 0; off >>= 1)
            v += __shfl_xor_sync(FULLM, v, off);
        z[q] = v;
    }
    if (lane == 0) {
        #pragma unroll
        for (int q = 0; q < NQ; ++q) out[b * NQ + q] = z[q];
    }
}

extern "C" void kernel_launch(void* const* d_in, const int* in_sizes, int n_in,
                              void* d_out, int out_size) {
    const float* xin = (const float*)d_in[0];   // [B, 10] f32
    const float* wts = (const float*)d_in[1];   // [4, 10, 3] f32
    float* out = (float*)d_out;                 // [B, 10] f32
    const int batch = in_sizes[0] / NQ;
    const int blocks = (batch + WPB - 1) / WPB;
    qsim_f32x2_kernel<<<blocks, NTHR>>>(xin, wts, out, batch);
}